// round 1
// baseline (speedup 1.0000x reference)
#include <cuda_runtime.h>
#include <math.h>

// Problem constants
// N=16, C=128, T=128, V=25, K=3, H=8, OC=256, C/H=16, OC/H=32, HOPMAX=12
// x: (16,128,128,25)  out: (16,256,128,25)

#define TV 3200          // T*V
#define CTV 409600       // C*T*V

// ---- scratch (device globals; allocation-free) ----
__device__ float d_BnA[24 * 625];            // [k*8+h][v*25+w]
__device__ float d_bsum[256];                // sum_k b_block[k*256+oc]
__device__ float d_res_pre[16 * 256 * 3200]; // 52.4 MB
__device__ float d_out_pre[16 * 256 * 3200]; // 52.4 MB
__device__ float d_ss[1024];                 // [scale_out|shift_out|scale_res|shift_res] x 256

// ---------------------------------------------------------------------------
// Kernel 1: build BnA = B/||B||_col + A/||A||_col, and summed bias.
// B[k,h,v,w] = emb_table[k,h,hop[v,w]]; column norm over v, + 1e-4.
// Blocks 0..23: one per (k,h); block 24: bias sum.
// ---------------------------------------------------------------------------
__global__ void prep_kernel(const int* __restrict__ hop,
                            const float* __restrict__ emb,
                            const float* __restrict__ A,
                            const float* __restrict__ b_block) {
    int g = blockIdx.x;
    int w = threadIdx.x;
    if (g < 24) {
        if (w < 25) {
            const float* eg = emb + g * 12;
            const float* Ag = A + g * 625;
            float sb = 0.f, sa = 0.f;
            for (int v = 0; v < 25; ++v) {
                float bv = eg[hop[v * 25 + w]];
                float av = Ag[v * 25 + w];
                sb += bv * bv;
                sa += av * av;
            }
            float rb = 1.f / (sqrtf(sb) + 1e-4f);
            float ra = 1.f / (sqrtf(sa) + 1e-4f);
            for (int v = 0; v < 25; ++v) {
                float bv = eg[hop[v * 25 + w]];
                float av = Ag[v * 25 + w];
                d_BnA[g * 625 + v * 25 + w] = bv * rb + av * ra;
            }
        }
    } else {
        for (int oc = w; oc < 256; oc += 32)
            d_bsum[oc] = b_block[oc] + b_block[256 + oc] + b_block[512 + oc];
    }
}

// ---------------------------------------------------------------------------
// Kernel 2: res_pre[n,o,tv] = sum_c res_w[o,c]*x[n,c,tv] + res_b[o]
// 128(o) x 128(tv) tile per block, 8x8 micro-tile per thread, K chunked by 16.
// ---------------------------------------------------------------------------
__global__ __launch_bounds__(256) void res_gemm_kernel(
    const float* __restrict__ x,
    const float* __restrict__ res_w,
    const float* __restrict__ res_b) {
    __shared__ float xs[16 * 132];   // [cc][tv_local], padded
    __shared__ float ws[128 * 17];   // [o_local][cc], padded

    int n = blockIdx.z;
    int o0 = blockIdx.y * 128;
    int tv0 = blockIdx.x * 128;
    int tid = threadIdx.x;
    int tx = tid & 15;   // tv group
    int ty = tid >> 4;   // o group

    float acc[8][8];
#pragma unroll
    for (int i = 0; i < 8; i++)
#pragma unroll
        for (int j = 0; j < 8; j++) acc[i][j] = 0.f;

    const float* xn = x + n * CTV;

    for (int c0 = 0; c0 < 128; c0 += 16) {
        __syncthreads();
#pragma unroll
        for (int it = 0; it < 8; it++) {
            int idx = tid + it * 256;
            int cc = idx >> 7, j = idx & 127;
            xs[cc * 132 + j] = xn[(c0 + cc) * TV + tv0 + j];
        }
#pragma unroll
        for (int it = 0; it < 8; it++) {
            int idx = tid + it * 256;
            int ol = idx >> 4, cc = idx & 15;
            ws[ol * 17 + cc] = res_w[(o0 + ol) * 128 + c0 + cc];
        }
        __syncthreads();

#pragma unroll
        for (int cc = 0; cc < 16; cc++) {
            float a[8], b[8];
#pragma unroll
            for (int i = 0; i < 8; i++) a[i] = ws[(ty * 8 + i) * 17 + cc];
            float4 b0 = *(const float4*)&xs[cc * 132 + tx * 8];
            float4 b1 = *(const float4*)&xs[cc * 132 + tx * 8 + 4];
            b[0] = b0.x; b[1] = b0.y; b[2] = b0.z; b[3] = b0.w;
            b[4] = b1.x; b[5] = b1.y; b[6] = b1.z; b[7] = b1.w;
#pragma unroll
            for (int i = 0; i < 8; i++)
#pragma unroll
                for (int j = 0; j < 8; j++) acc[i][j] += a[i] * b[j];
        }
    }

#pragma unroll
    for (int i = 0; i < 8; i++) {
        int o = o0 + ty * 8 + i;
        float bias = res_b[o];
        float* dst = d_res_pre + (n * 256 + o) * TV + tv0 + tx * 8;
        float4 v0 = make_float4(acc[i][0] + bias, acc[i][1] + bias,
                                acc[i][2] + bias, acc[i][3] + bias);
        float4 v1 = make_float4(acc[i][4] + bias, acc[i][5] + bias,
                                acc[i][6] + bias, acc[i][7] + bias);
        *(float4*)dst = v0;
        *(float4*)(dst + 4) = v1;
    }
}

// ---------------------------------------------------------------------------
// Kernel 3: main path.
// Per block: one (n, h, 16-row t tile).
// out_pre[n, h*32+o', t, w] = sum_k sum_c' wg[k,h,o',c'] * (sum_v x[n,h,c',t,v]*BnA[k,h,v,w])
//                             + bsum[h*32+o']
// Thread = (t, w) position; accumulates 32 o' outputs in registers.
// ---------------------------------------------------------------------------
__global__ __launch_bounds__(400) void main_kernel(
    const float* __restrict__ x,
    const float* __restrict__ w_block) {
    __shared__ float xs[16 * 400];    // [c'][t*25+v]
    __shared__ float bna_s[3 * 625];  // [k][v*25+w]
    __shared__ float wg_s[3 * 512];   // [k][o'*16+c']

    int t0 = blockIdx.x * 16;
    int h = blockIdx.y;
    int n = blockIdx.z;
    int tid = threadIdx.x;

    const float* xb = x + n * CTV + h * 16 * TV + t0 * 25;
#pragma unroll
    for (int c = 0; c < 16; ++c)
        xs[c * 400 + tid] = xb[c * TV + tid];
    for (int idx = tid; idx < 1875; idx += 400) {
        int k = idx / 625, vw = idx - k * 625;
        bna_s[idx] = d_BnA[(k * 8 + h) * 625 + vw];
    }
    for (int idx = tid; idx < 1536; idx += 400) {
        int k = idx >> 9, r = idx & 511;
        wg_s[idx] = w_block[(k * 8 + h) * 512 + r];
    }
    __syncthreads();

    int t = tid / 25;
    int w = tid - t * 25;

    float acc[32];
#pragma unroll
    for (int o = 0; o < 32; o++) acc[o] = 0.f;

    for (int k = 0; k < 3; ++k) {
        float bn[25];
#pragma unroll
        for (int v = 0; v < 25; v++) bn[v] = bna_s[k * 625 + v * 25 + w];
        float y[16];
#pragma unroll
        for (int c = 0; c < 16; c++) {
            float s = 0.f;
#pragma unroll
            for (int v = 0; v < 25; v++) s += xs[c * 400 + t * 25 + v] * bn[v];
            y[c] = s;
        }
#pragma unroll
        for (int o = 0; o < 32; o++) {
            float s = 0.f;
#pragma unroll
            for (int c = 0; c < 16; c++) s += wg_s[k * 512 + o * 16 + c] * y[c];
            acc[o] += s;
        }
    }

    int ocb = h * 32;
    float* dst = d_out_pre + (n * 256 + ocb) * TV + (t0 + t) * 25 + w;
#pragma unroll
    for (int o = 0; o < 32; o++)
        dst[o * TV] = acc[o] + d_bsum[ocb + o];
}

// ---------------------------------------------------------------------------
// Kernel 4: per-channel BN stats -> scale/shift. One block per (which, channel).
// Deterministic (no atomics).
// ---------------------------------------------------------------------------
__global__ __launch_bounds__(256) void stats_kernel(
    const float* __restrict__ bn_gamma, const float* __restrict__ bn_beta,
    const float* __restrict__ res_bn_gamma, const float* __restrict__ res_bn_beta) {
    __shared__ float ssum[256];
    __shared__ float ssq[256];
    int ch = blockIdx.x & 255;
    int which = blockIdx.x >> 8;  // 0 = out path, 1 = res path
    const float* src = (which ? d_res_pre : d_out_pre) + ch * TV;
    int tid = threadIdx.x;

    float s = 0.f, q = 0.f;
    for (int n = 0; n < 16; ++n) {
        const float* p = src + n * 256 * TV;
        for (int i = tid; i < TV; i += 256) {
            float v = p[i];
            s += v;
            q += v * v;
        }
    }
    ssum[tid] = s;
    ssq[tid] = q;
    __syncthreads();
    for (int st = 128; st > 0; st >>= 1) {
        if (tid < st) {
            ssum[tid] += ssum[tid + st];
            ssq[tid] += ssq[tid + st];
        }
        __syncthreads();
    }
    if (tid == 0) {
        const float inv = 1.f / 51200.f;  // N*T*V
        float mean = ssum[0] * inv;
        float var = ssq[0] * inv - mean * mean;
        float g = which ? res_bn_gamma[ch] : bn_gamma[ch];
        float b = which ? res_bn_beta[ch] : bn_beta[ch];
        float sc = g * rsqrtf(var + 1e-5f);
        d_ss[which * 512 + ch] = sc;
        d_ss[which * 512 + 256 + ch] = b - mean * sc;
    }
}

// ---------------------------------------------------------------------------
// Kernel 5: out = relu(BN(out_pre) + BN(res_pre)), vectorized float4.
// ---------------------------------------------------------------------------
__global__ __launch_bounds__(256) void final_kernel(float* __restrict__ out) {
    int idx4 = blockIdx.x * 256 + threadIdx.x;
    int flat = idx4 * 4;
    int ch = (flat / TV) & 255;
    float4 op = *(const float4*)(d_out_pre + flat);
    float4 rp = *(const float4*)(d_res_pre + flat);
    float so = d_ss[ch], ho = d_ss[256 + ch];
    float sr = d_ss[512 + ch], hr = d_ss[768 + ch];
    float4 r;
    r.x = fmaxf(fmaf(op.x, so, ho) + fmaf(rp.x, sr, hr), 0.f);
    r.y = fmaxf(fmaf(op.y, so, ho) + fmaf(rp.y, sr, hr), 0.f);
    r.z = fmaxf(fmaf(op.z, so, ho) + fmaf(rp.z, sr, hr), 0.f);
    r.w = fmaxf(fmaf(op.w, so, ho) + fmaf(rp.w, sr, hr), 0.f);
    *(float4*)(out + flat) = r;
}

// ---------------------------------------------------------------------------
extern "C" void kernel_launch(void* const* d_in, const int* in_sizes, int n_in,
                              void* d_out, int out_size) {
    const float* x            = (const float*)d_in[0];
    const int*   hop          = (const int*)d_in[1];
    const float* emb          = (const float*)d_in[2];
    const float* A            = (const float*)d_in[3];
    const float* w_block      = (const float*)d_in[4];
    const float* b_block      = (const float*)d_in[5];
    const float* bn_gamma     = (const float*)d_in[6];
    const float* bn_beta      = (const float*)d_in[7];
    const float* res_w        = (const float*)d_in[8];
    const float* res_b        = (const float*)d_in[9];
    const float* res_bn_gamma = (const float*)d_in[10];
    const float* res_bn_beta  = (const float*)d_in[11];
    float* out = (float*)d_out;

    prep_kernel<<<25, 32>>>(hop, emb, A, b_block);
    res_gemm_kernel<<<dim3(25, 2, 16), 256>>>(x, res_w, res_b);
    main_kernel<<<dim3(8, 8, 16), 400>>>(x, w_block);
    stats_kernel<<<512, 256>>>(bn_gamma, bn_beta, res_bn_gamma, res_bn_beta);
    final_kernel<<<12800, 256>>>(out);
}

// round 2
// speedup vs baseline: 2.3336x; 2.3336x over previous
#include <cuda_runtime.h>
#include <math.h>

// Problem constants
// N=16, C=128, T=128, V=25, K=3, H=8, OC=256, C/H=16, OC/H=32, HOPMAX=12
// x: (16,128,128,25)  out: (16,256,128,25)

#define TV 3200          // T*V
#define CTV 409600       // C*T*V

// ---- scratch (device globals; allocation-free) ----
__device__ float d_BnA[24 * 625];            // [k*8+h][v*25+w]
__device__ float d_bsum[256];                // sum_k b_block[k*256+oc]
__device__ float d_res_pre[16 * 256 * 3200]; // 52.4 MB
__device__ float d_out_pre[16 * 256 * 3200]; // 52.4 MB
__device__ float d_ss[1024];                 // [scale_out|shift_out|scale_res|shift_res] x 256

// ---------------------------------------------------------------------------
// Kernel 1: build BnA = B/||B||_col + A/||A||_col, and summed bias.
// ---------------------------------------------------------------------------
__global__ void prep_kernel(const int* __restrict__ hop,
                            const float* __restrict__ emb,
                            const float* __restrict__ A,
                            const float* __restrict__ b_block) {
    int g = blockIdx.x;
    int w = threadIdx.x;
    if (g < 24) {
        if (w < 25) {
            const float* eg = emb + g * 12;
            const float* Ag = A + g * 625;
            float sb = 0.f, sa = 0.f;
            for (int v = 0; v < 25; ++v) {
                float bv = eg[hop[v * 25 + w]];
                float av = Ag[v * 25 + w];
                sb += bv * bv;
                sa += av * av;
            }
            float rb = 1.f / (sqrtf(sb) + 1e-4f);
            float ra = 1.f / (sqrtf(sa) + 1e-4f);
            for (int v = 0; v < 25; ++v) {
                float bv = eg[hop[v * 25 + w]];
                float av = Ag[v * 25 + w];
                d_BnA[g * 625 + v * 25 + w] = bv * rb + av * ra;
            }
        }
    } else {
        for (int oc = w; oc < 256; oc += 32)
            d_bsum[oc] = b_block[oc] + b_block[256 + oc] + b_block[512 + oc];
    }
}

// ---------------------------------------------------------------------------
// Kernel 2: res_pre[n,o,tv] = sum_c res_w[o,c]*x[n,c,tv] + res_b[o]
// 128(o) x 128(tv) tile per block, 8x8 micro-tile per thread, K chunked by 16.
// Weight tile stored transposed [cc][o] so A-fragments are broadcast LDS.128.
// ---------------------------------------------------------------------------
__global__ __launch_bounds__(256) void res_gemm_kernel(
    const float* __restrict__ x,
    const float* __restrict__ res_w,
    const float* __restrict__ res_b) {
    __shared__ __align__(16) float xs[16 * 136];   // [cc][tv_local], 16B-aligned rows
    __shared__ __align__(16) float ws[16 * 136];   // [cc][o_local]

    int n = blockIdx.z;
    int o0 = blockIdx.y * 128;
    int tv0 = blockIdx.x * 128;
    int tid = threadIdx.x;
    int tx = tid & 15;   // tv group
    int ty = tid >> 4;   // o group

    float acc[8][8];
#pragma unroll
    for (int i = 0; i < 8; i++)
#pragma unroll
        for (int j = 0; j < 8; j++) acc[i][j] = 0.f;

    const float* xn = x + n * CTV;

    for (int c0 = 0; c0 < 128; c0 += 16) {
        __syncthreads();
        // x tile: 16 cc x 128 tv = 512 float4 loads (coalesced), store aligned
#pragma unroll
        for (int it = 0; it < 2; it++) {
            int slot = tid + it * 256;       // 0..511
            int cc = slot >> 5, j4 = slot & 31;
            float4 v = *(const float4*)&xn[(c0 + cc) * TV + tv0 + j4 * 4];
            *(float4*)&xs[cc * 136 + j4 * 4] = v;
        }
        // w tile: read [ol][cc] coalesced, write transposed [cc][ol]
#pragma unroll
        for (int it = 0; it < 8; it++) {
            int idx = tid + it * 256;
            int ol = idx >> 4, cc = idx & 15;
            ws[cc * 136 + ol] = res_w[(o0 + ol) * 128 + c0 + cc];
        }
        __syncthreads();

#pragma unroll
        for (int cc = 0; cc < 16; cc++) {
            float a[8], b[8];
            float4 a0 = *(const float4*)&ws[cc * 136 + ty * 8];
            float4 a1 = *(const float4*)&ws[cc * 136 + ty * 8 + 4];
            a[0] = a0.x; a[1] = a0.y; a[2] = a0.z; a[3] = a0.w;
            a[4] = a1.x; a[5] = a1.y; a[6] = a1.z; a[7] = a1.w;
            float4 b0 = *(const float4*)&xs[cc * 136 + tx * 8];
            float4 b1 = *(const float4*)&xs[cc * 136 + tx * 8 + 4];
            b[0] = b0.x; b[1] = b0.y; b[2] = b0.z; b[3] = b0.w;
            b[4] = b1.x; b[5] = b1.y; b[6] = b1.z; b[7] = b1.w;
#pragma unroll
            for (int i = 0; i < 8; i++)
#pragma unroll
                for (int j = 0; j < 8; j++) acc[i][j] += a[i] * b[j];
        }
    }

#pragma unroll
    for (int i = 0; i < 8; i++) {
        int o = o0 + ty * 8 + i;
        float bias = res_b[o];
        float* dst = d_res_pre + (n * 256 + o) * TV + tv0 + tx * 8;
        float4 v0 = make_float4(acc[i][0] + bias, acc[i][1] + bias,
                                acc[i][2] + bias, acc[i][3] + bias);
        float4 v1 = make_float4(acc[i][4] + bias, acc[i][5] + bias,
                                acc[i][6] + bias, acc[i][7] + bias);
        *(float4*)dst = v0;
        *(float4*)(dst + 4) = v1;
    }
}

// ---------------------------------------------------------------------------
// Kernel 3: main path. Per block: one (n, h, 8-row t tile). 200 threads.
// Thread = (t, w); accumulates 32 o' outputs. x rows padded to 28 floats so
// stage-1 reads are LDS.128; wg stored [k][c][o] so stage-2 reads are
// broadcast LDS.128.
// ---------------------------------------------------------------------------
__global__ __launch_bounds__(200, 3) void main_kernel(
    const float* __restrict__ x,
    const float* __restrict__ w_block) {
    __shared__ __align__(16) float xs[16 * 224];   // [c][t*28+v], t<8, pad 28
    __shared__ float bna_s[3 * 625];               // [k][v*25+w]
    __shared__ __align__(16) float wg_s[3 * 512];  // [k][c*32+o]

    int t0 = blockIdx.x * 8;
    int h = blockIdx.y;
    int n = blockIdx.z;
    int tid = threadIdx.x;
    int t = tid / 25;
    int w = tid - t * 25;

    const float* xb = x + n * CTV + h * 16 * TV + t0 * 25;
#pragma unroll
    for (int c = 0; c < 16; ++c)
        xs[c * 224 + t * 28 + w] = xb[c * TV + tid];
    for (int idx = tid; idx < 1875; idx += 200) {
        int k = idx / 625, vw = idx - k * 625;
        bna_s[idx] = d_BnA[(k * 8 + h) * 625 + vw];
    }
    for (int idx = tid; idx < 1536; idx += 200) {
        int k = idx >> 9, r = idx & 511;
        int o = (r >> 4), c = (r & 15);           // w_block row layout [o][c]
        wg_s[k * 512 + c * 32 + o] = w_block[(k * 8 + h) * 512 + r];
    }
    __syncthreads();

    float acc[32];
#pragma unroll
    for (int o = 0; o < 32; o++) acc[o] = 0.f;

    for (int k = 0; k < 3; ++k) {
        float bn[25];
#pragma unroll
        for (int v = 0; v < 25; v++) bn[v] = bna_s[k * 625 + v * 25 + w];
#pragma unroll 4
        for (int c = 0; c < 16; ++c) {
            const float* xr = &xs[c * 224 + t * 28];
            float4 a0 = *(const float4*)(xr + 0);
            float4 a1 = *(const float4*)(xr + 4);
            float4 a2 = *(const float4*)(xr + 8);
            float4 a3 = *(const float4*)(xr + 12);
            float4 a4 = *(const float4*)(xr + 16);
            float4 a5 = *(const float4*)(xr + 20);
            float la = xr[24];
            // 4 independent partial chains for ILP
            float y0 = a0.x * bn[0];
            float y1 = a0.y * bn[1];
            float y2 = a0.z * bn[2];
            float y3 = a0.w * bn[3];
            y0 += a1.x * bn[4];  y1 += a1.y * bn[5];
            y2 += a1.z * bn[6];  y3 += a1.w * bn[7];
            y0 += a2.x * bn[8];  y1 += a2.y * bn[9];
            y2 += a2.z * bn[10]; y3 += a2.w * bn[11];
            y0 += a3.x * bn[12]; y1 += a3.y * bn[13];
            y2 += a3.z * bn[14]; y3 += a3.w * bn[15];
            y0 += a4.x * bn[16]; y1 += a4.y * bn[17];
            y2 += a4.z * bn[18]; y3 += a4.w * bn[19];
            y0 += a5.x * bn[20]; y1 += a5.y * bn[21];
            y2 += a5.z * bn[22]; y3 += a5.w * bn[23];
            y0 += la * bn[24];
            float y = (y0 + y1) + (y2 + y3);

            const float* wr = &wg_s[k * 512 + c * 32];
#pragma unroll
            for (int o4 = 0; o4 < 8; o4++) {
                float4 wv = *(const float4*)(wr + o4 * 4);
                acc[o4 * 4 + 0] += wv.x * y;
                acc[o4 * 4 + 1] += wv.y * y;
                acc[o4 * 4 + 2] += wv.z * y;
                acc[o4 * 4 + 3] += wv.w * y;
            }
        }
    }

    int ocb = h * 32;
    float* dst = d_out_pre + (n * 256 + ocb) * TV + (t0 + t) * 25 + w;
#pragma unroll
    for (int o = 0; o < 32; o++)
        dst[o * TV] = acc[o] + d_bsum[ocb + o];
}

// ---------------------------------------------------------------------------
// Kernel 4: per-channel BN stats -> scale/shift. One block per (which, channel).
// Deterministic; float4 loads.
// ---------------------------------------------------------------------------
__global__ __launch_bounds__(256) void stats_kernel(
    const float* __restrict__ bn_gamma, const float* __restrict__ bn_beta,
    const float* __restrict__ res_bn_gamma, const float* __restrict__ res_bn_beta) {
    __shared__ float ssum[256];
    __shared__ float ssq[256];
    int ch = blockIdx.x & 255;
    int which = blockIdx.x >> 8;  // 0 = out path, 1 = res path
    const float* src = (which ? d_res_pre : d_out_pre) + ch * TV;
    int tid = threadIdx.x;

    float s = 0.f, q = 0.f;
    for (int n = 0; n < 16; ++n) {
        const float4* p = (const float4*)(src + n * 256 * TV);
        for (int i = tid; i < 800; i += 256) {
            float4 v = p[i];
            s += (v.x + v.y) + (v.z + v.w);
            q += v.x * v.x + v.y * v.y + v.z * v.z + v.w * v.w;
        }
    }
    ssum[tid] = s;
    ssq[tid] = q;
    __syncthreads();
    for (int st = 128; st > 0; st >>= 1) {
        if (tid < st) {
            ssum[tid] += ssum[tid + st];
            ssq[tid] += ssq[tid + st];
        }
        __syncthreads();
    }
    if (tid == 0) {
        const float inv = 1.f / 51200.f;  // N*T*V
        float mean = ssum[0] * inv;
        float var = ssq[0] * inv - mean * mean;
        float g = which ? res_bn_gamma[ch] : bn_gamma[ch];
        float b = which ? res_bn_beta[ch] : bn_beta[ch];
        float sc = g * rsqrtf(var + 1e-5f);
        d_ss[which * 512 + ch] = sc;
        d_ss[which * 512 + 256 + ch] = b - mean * sc;
    }
}

// ---------------------------------------------------------------------------
// Kernel 5: out = relu(BN(out_pre) + BN(res_pre)), vectorized float4.
// ---------------------------------------------------------------------------
__global__ __launch_bounds__(256) void final_kernel(float* __restrict__ out) {
    int idx4 = blockIdx.x * 256 + threadIdx.x;
    int flat = idx4 * 4;
    int ch = (flat / TV) & 255;
    float4 op = *(const float4*)(d_out_pre + flat);
    float4 rp = *(const float4*)(d_res_pre + flat);
    float so = d_ss[ch], ho = d_ss[256 + ch];
    float sr = d_ss[512 + ch], hr = d_ss[768 + ch];
    float4 r;
    r.x = fmaxf(fmaf(op.x, so, ho) + fmaf(rp.x, sr, hr), 0.f);
    r.y = fmaxf(fmaf(op.y, so, ho) + fmaf(rp.y, sr, hr), 0.f);
    r.z = fmaxf(fmaf(op.z, so, ho) + fmaf(rp.z, sr, hr), 0.f);
    r.w = fmaxf(fmaf(op.w, so, ho) + fmaf(rp.w, sr, hr), 0.f);
    *(float4*)(out + flat) = r;
}

// ---------------------------------------------------------------------------
extern "C" void kernel_launch(void* const* d_in, const int* in_sizes, int n_in,
                              void* d_out, int out_size) {
    const float* x            = (const float*)d_in[0];
    const int*   hop          = (const int*)d_in[1];
    const float* emb          = (const float*)d_in[2];
    const float* A            = (const float*)d_in[3];
    const float* w_block      = (const float*)d_in[4];
    const float* b_block      = (const float*)d_in[5];
    const float* bn_gamma     = (const float*)d_in[6];
    const float* bn_beta      = (const float*)d_in[7];
    const float* res_w        = (const float*)d_in[8];
    const float* res_b        = (const float*)d_in[9];
    const float* res_bn_gamma = (const float*)d_in[10];
    const float* res_bn_beta  = (const float*)d_in[11];
    float* out = (float*)d_out;

    prep_kernel<<<25, 32>>>(hop, emb, A, b_block);
    res_gemm_kernel<<<dim3(25, 2, 16), 256>>>(x, res_w, res_b);
    main_kernel<<<dim3(16, 8, 16), 200>>>(x, w_block);
    stats_kernel<<<512, 256>>>(bn_gamma, bn_beta, res_bn_gamma, res_bn_beta);
    final_kernel<<<12800, 256>>>(out);
}

// round 4
// speedup vs baseline: 2.9649x; 1.2705x over previous
#include <cuda_runtime.h>
#include <math.h>
#include <stdint.h>

// Problem constants
// N=16, C=128, T=128, V=25, K=3, H=8, OC=256, C/H=16, OC/H=32
// x: (16,128,128,25)  out: (16,256,128,25)

#define TV 3200          // T*V
#define CTV 409600       // C*T*V

// ---- scratch (device globals; allocation-free) ----
__device__ float d_BnA[24 * 625];
__device__ float d_bsum[256];
__device__ float d_res_pre[16 * 256 * 3200]; // 52.4 MB
__device__ float d_out_pre[16 * 256 * 3200]; // 52.4 MB
__device__ float d_ss[1024];
// res-path BN partials: [(n*2+ob)*25+tvb][row(128)*2]  (sum, sumsq)
__device__ float d_rpart[800 * 256];

__device__ __forceinline__ uint32_t f2tf32(float f) {
    uint32_t r;
    asm("cvt.rna.tf32.f32 %0, %1;" : "=r"(r) : "f"(f));
    return r;
}

__device__ __forceinline__ void mma_tf32(float c[4], const uint32_t a[4],
                                         const uint32_t b[2]) {
    asm volatile(
        "mma.sync.aligned.m16n8k8.row.col.f32.tf32.tf32.f32 "
        "{%0,%1,%2,%3},{%4,%5,%6,%7},{%8,%9},{%0,%1,%2,%3};"
        : "+f"(c[0]), "+f"(c[1]), "+f"(c[2]), "+f"(c[3])
        : "r"(a[0]), "r"(a[1]), "r"(a[2]), "r"(a[3]), "r"(b[0]), "r"(b[1]));
}

// ---------------------------------------------------------------------------
// Kernel 1: build BnA and summed bias.
// ---------------------------------------------------------------------------
__global__ void prep_kernel(const int* __restrict__ hop,
                            const float* __restrict__ emb,
                            const float* __restrict__ A,
                            const float* __restrict__ b_block) {
    int g = blockIdx.x;
    int w = threadIdx.x;
    if (g < 24) {
        if (w < 25) {
            const float* eg = emb + g * 12;
            const float* Ag = A + g * 625;
            float sb = 0.f, sa = 0.f;
            for (int v = 0; v < 25; ++v) {
                float bv = eg[hop[v * 25 + w]];
                float av = Ag[v * 25 + w];
                sb += bv * bv;
                sa += av * av;
            }
            float rb = 1.f / (sqrtf(sb) + 1e-4f);
            float ra = 1.f / (sqrtf(sa) + 1e-4f);
            for (int v = 0; v < 25; ++v) {
                float bv = eg[hop[v * 25 + w]];
                float av = Ag[v * 25 + w];
                d_BnA[g * 625 + v * 25 + w] = bv * rb + av * ra;
            }
        }
    } else {
        for (int oc = w; oc < 256; oc += 32)
            d_bsum[oc] = b_block[oc] + b_block[256 + oc] + b_block[512 + oc];
    }
}

// ---------------------------------------------------------------------------
// Kernel 2: res GEMM on mma.sync tf32 (m16n8k8).
// CTA: D[128 o][128 tv], K = 128 c. smem rows stride 132 words (conflict-free
// fragment LDS: 132 mod 32 == 4). 8 warps = 4(m) x 2(n); warp tile 32x64.
// Epilogue: bias add, direct STG.64, and per-channel (sum,sumsq) partials.
// ---------------------------------------------------------------------------
#define RES_SMEM_BYTES ((16896 + 16896 + 512) * 4)

__global__ __launch_bounds__(256) void res_gemm_tc(
    const float* __restrict__ x,
    const float* __restrict__ res_w,
    const float* __restrict__ res_b) {
    extern __shared__ __align__(16) float smem[];
    float* As = smem;               // [o(128)][k stride 132]
    float* Bs = smem + 16896;       // [tv(128)][k stride 132]
    float* part = smem + 33792;     // [warp_n(2)][row(128)][2]

    const int tid = threadIdx.x;
    const int wid = tid >> 5, lane = tid & 31;
    const int gid = lane >> 2, tg = lane & 3;
    const int warp_m = wid >> 1;    // 0..3 -> M offset 32 each
    const int warp_n = wid & 1;     // 0..1 -> N offset 64 each
    const int tv0 = blockIdx.x * 128;
    const int o0 = blockIdx.y * 128;
    const int n = blockIdx.z;

    // Stage A: res_w[o0+o][c] -> As[o][c], tf32, STS.128
    {
        const float4* wsrc = (const float4*)(res_w + o0 * 128);
#pragma unroll
        for (int it = 0; it < 16; ++it) {
            int idx = tid + it * 256;            // 0..4095
            int o = idx >> 5, c4 = idx & 31;
            float4 v = wsrc[o * 32 + c4];
            uint4 t;
            t.x = f2tf32(v.x); t.y = f2tf32(v.y);
            t.z = f2tf32(v.z); t.w = f2tf32(v.w);
            *(uint4*)(As + o * 132 + c4 * 4) = t;
        }
    }
    // Stage B: x[n][c][tv0+j] -> Bs[j][c] (transposed), tf32
    {
        const float* xn = x + n * CTV + tv0;
#pragma unroll
        for (int it = 0; it < 16; ++it) {
            int idx = tid + it * 256;            // 0..4095
            int c = idx >> 5, j4 = idx & 31;
            float4 v = *(const float4*)(xn + c * TV + j4 * 4);
            uint32_t* b = (uint32_t*)Bs;
            b[(j4 * 4 + 0) * 132 + c] = f2tf32(v.x);
            b[(j4 * 4 + 1) * 132 + c] = f2tf32(v.y);
            b[(j4 * 4 + 2) * 132 + c] = f2tf32(v.z);
            b[(j4 * 4 + 3) * 132 + c] = f2tf32(v.w);
        }
    }
    __syncthreads();

    float c[2][8][4];
#pragma unroll
    for (int mt = 0; mt < 2; ++mt)
#pragma unroll
        for (int nt = 0; nt < 8; ++nt)
#pragma unroll
            for (int q = 0; q < 4; ++q) c[mt][nt][q] = 0.f;

    const uint32_t* Au = (const uint32_t*)As;
    const uint32_t* Bu = (const uint32_t*)Bs;
    const int arow = (warp_m * 32 + gid) * 132 + tg;    // + mt*16*132, +k0
    const int brow = (warp_n * 64 + gid) * 132 + tg;    // + nt*8*132, +k0

#pragma unroll
    for (int step = 0; step < 16; ++step) {
        const int k0 = step * 8;
        uint32_t a[2][4], b[8][2];
#pragma unroll
        for (int mt = 0; mt < 2; ++mt) {
            int base = arow + mt * 16 * 132 + k0;
            a[mt][0] = Au[base];
            a[mt][1] = Au[base + 8 * 132];
            a[mt][2] = Au[base + 4];
            a[mt][3] = Au[base + 8 * 132 + 4];
        }
#pragma unroll
        for (int nt = 0; nt < 8; ++nt) {
            int base = brow + nt * 8 * 132 + k0;
            b[nt][0] = Bu[base];
            b[nt][1] = Bu[base + 4];
        }
#pragma unroll
        for (int mt = 0; mt < 2; ++mt)
#pragma unroll
            for (int nt = 0; nt < 8; ++nt)
                mma_tf32(c[mt][nt], a[mt], b[nt]);
    }

    // Epilogue: bias, store, per-row stats partials.
    const int colbase = tv0 + warp_n * 64 + 2 * tg;
#pragma unroll
    for (int mt = 0; mt < 2; ++mt) {
        int row0 = o0 + warp_m * 32 + mt * 16 + gid;   // rows row0, row0+8
        float bias0 = res_b[row0];
        float bias1 = res_b[row0 + 8];
        float s0 = 0.f, q0 = 0.f, s1 = 0.f, q1 = 0.f;
        float* dst0 = d_res_pre + (n * 256 + row0) * TV;
        float* dst1 = dst0 + 8 * TV;
#pragma unroll
        for (int nt = 0; nt < 8; ++nt) {
            float v0 = c[mt][nt][0] + bias0;
            float v1 = c[mt][nt][1] + bias0;
            float v2 = c[mt][nt][2] + bias1;
            float v3 = c[mt][nt][3] + bias1;
            s0 += v0 + v1;  q0 += v0 * v0 + v1 * v1;
            s1 += v2 + v3;  q1 += v2 * v2 + v3 * v3;
            int col = colbase + nt * 8;
            *(float2*)(dst0 + col) = make_float2(v0, v1);
            *(float2*)(dst1 + col) = make_float2(v2, v3);
        }
        // quad reduce (lanes tg 0..3 share the same rows)
#pragma unroll
        for (int off = 1; off <= 2; off <<= 1) {
            s0 += __shfl_xor_sync(0xFFFFFFFFu, s0, off);
            q0 += __shfl_xor_sync(0xFFFFFFFFu, q0, off);
            s1 += __shfl_xor_sync(0xFFFFFFFFu, s1, off);
            q1 += __shfl_xor_sync(0xFFFFFFFFu, q1, off);
        }
        if (tg == 0) {
            int r = warp_m * 32 + mt * 16 + gid;
            part[(warp_n * 128 + r) * 2] = s0;
            part[(warp_n * 128 + r) * 2 + 1] = q0;
            part[(warp_n * 128 + r + 8) * 2] = s1;
            part[(warp_n * 128 + r + 8) * 2 + 1] = q1;
        }
    }
    __syncthreads();
    if (tid < 128) {
        float s = part[tid * 2] + part[(128 + tid) * 2];
        float q = part[tid * 2 + 1] + part[(128 + tid) * 2 + 1];
        int blk = (n * 2 + blockIdx.y) * 25 + blockIdx.x;
        d_rpart[blk * 256 + tid * 2] = s;
        d_rpart[blk * 256 + tid * 2 + 1] = q;
    }
}

// ---------------------------------------------------------------------------
// Kernel 3: main path (fp32, as before).
// ---------------------------------------------------------------------------
__global__ __launch_bounds__(200, 3) void main_kernel(
    const float* __restrict__ x,
    const float* __restrict__ w_block) {
    __shared__ __align__(16) float xs[16 * 224];
    __shared__ float bna_s[3 * 625];
    __shared__ __align__(16) float wg_s[3 * 512];

    int t0 = blockIdx.x * 8;
    int h = blockIdx.y;
    int n = blockIdx.z;
    int tid = threadIdx.x;
    int t = tid / 25;
    int w = tid - t * 25;

    const float* xb = x + n * CTV + h * 16 * TV + t0 * 25;
#pragma unroll
    for (int c = 0; c < 16; ++c)
        xs[c * 224 + t * 28 + w] = xb[c * TV + tid];
    for (int idx = tid; idx < 1875; idx += 200) {
        int k = idx / 625, vw = idx - k * 625;
        bna_s[idx] = d_BnA[(k * 8 + h) * 625 + vw];
    }
    for (int idx = tid; idx < 1536; idx += 200) {
        int k = idx >> 9, r = idx & 511;
        int o = (r >> 4), c = (r & 15);
        wg_s[k * 512 + c * 32 + o] = w_block[(k * 8 + h) * 512 + r];
    }
    __syncthreads();

    float acc[32];
#pragma unroll
    for (int o = 0; o < 32; o++) acc[o] = 0.f;

    for (int k = 0; k < 3; ++k) {
        float bn[25];
#pragma unroll
        for (int v = 0; v < 25; v++) bn[v] = bna_s[k * 625 + v * 25 + w];
#pragma unroll 4
        for (int c = 0; c < 16; ++c) {
            const float* xr = &xs[c * 224 + t * 28];
            float4 a0 = *(const float4*)(xr + 0);
            float4 a1 = *(const float4*)(xr + 4);
            float4 a2 = *(const float4*)(xr + 8);
            float4 a3 = *(const float4*)(xr + 12);
            float4 a4 = *(const float4*)(xr + 16);
            float4 a5 = *(const float4*)(xr + 20);
            float la = xr[24];
            float y0 = a0.x * bn[0];
            float y1 = a0.y * bn[1];
            float y2 = a0.z * bn[2];
            float y3 = a0.w * bn[3];
            y0 += a1.x * bn[4];  y1 += a1.y * bn[5];
            y2 += a1.z * bn[6];  y3 += a1.w * bn[7];
            y0 += a2.x * bn[8];  y1 += a2.y * bn[9];
            y2 += a2.z * bn[10]; y3 += a2.w * bn[11];
            y0 += a3.x * bn[12]; y1 += a3.y * bn[13];
            y2 += a3.z * bn[14]; y3 += a3.w * bn[15];
            y0 += a4.x * bn[16]; y1 += a4.y * bn[17];
            y2 += a4.z * bn[18]; y3 += a4.w * bn[19];
            y0 += a5.x * bn[20]; y1 += a5.y * bn[21];
            y2 += a5.z * bn[22]; y3 += a5.w * bn[23];
            y0 += la * bn[24];
            float y = (y0 + y1) + (y2 + y3);

            const float* wr = &wg_s[k * 512 + c * 32];
#pragma unroll
            for (int o4 = 0; o4 < 8; o4++) {
                float4 wv = *(const float4*)(wr + o4 * 4);
                acc[o4 * 4 + 0] += wv.x * y;
                acc[o4 * 4 + 1] += wv.y * y;
                acc[o4 * 4 + 2] += wv.z * y;
                acc[o4 * 4 + 3] += wv.w * y;
            }
        }
    }

    int ocb = h * 32;
    float* dst = d_out_pre + (n * 256 + ocb) * TV + (t0 + t) * 25 + w;
#pragma unroll
    for (int o = 0; o < 32; o++)
        dst[o * TV] = acc[o] + d_bsum[ocb + o];
}

// ---------------------------------------------------------------------------
// Kernel 4a: out-path BN stats (full read of d_out_pre). One block / channel.
// ---------------------------------------------------------------------------
__global__ __launch_bounds__(512) void stats_kernel(
    const float* __restrict__ bn_gamma, const float* __restrict__ bn_beta) {
    __shared__ float ssum[512];
    __shared__ float ssq[512];
    int ch = blockIdx.x;
    const float4* src = (const float4*)(d_out_pre + ch * TV);
    int tid = threadIdx.x;

    float s0 = 0.f, q0 = 0.f, s1 = 0.f, q1 = 0.f;
    float s2 = 0.f, q2 = 0.f, s3 = 0.f, q3 = 0.f;
#pragma unroll
    for (int it = 0; it < 25; ++it) {
        int idx = tid + it * 512;
        int nn = idx / 800;
        int r = idx - nn * 800;
        float4 v = src[nn * 204800 + r];
        if ((it & 3) == 0) { s0 += (v.x + v.y) + (v.z + v.w); q0 += v.x*v.x + v.y*v.y + v.z*v.z + v.w*v.w; }
        else if ((it & 3) == 1) { s1 += (v.x + v.y) + (v.z + v.w); q1 += v.x*v.x + v.y*v.y + v.z*v.z + v.w*v.w; }
        else if ((it & 3) == 2) { s2 += (v.x + v.y) + (v.z + v.w); q2 += v.x*v.x + v.y*v.y + v.z*v.z + v.w*v.w; }
        else { s3 += (v.x + v.y) + (v.z + v.w); q3 += v.x*v.x + v.y*v.y + v.z*v.z + v.w*v.w; }
    }
    ssum[tid] = (s0 + s1) + (s2 + s3);
    ssq[tid] = (q0 + q1) + (q2 + q3);
    __syncthreads();
    for (int st = 256; st > 0; st >>= 1) {
        if (tid < st) {
            ssum[tid] += ssum[tid + st];
            ssq[tid] += ssq[tid + st];
        }
        __syncthreads();
    }
    if (tid == 0) {
        const float inv = 1.f / 51200.f;
        float mean = ssum[0] * inv;
        float var = ssq[0] * inv - mean * mean;
        float sc = bn_gamma[ch] * rsqrtf(var + 1e-5f);
        d_ss[ch] = sc;
        d_ss[256 + ch] = bn_beta[ch] - mean * sc;
    }
}

// ---------------------------------------------------------------------------
// Kernel 4b: res-path BN stats from GEMM partials. One block / channel.
// ---------------------------------------------------------------------------
__global__ __launch_bounds__(128) void stats_res_kernel(
    const float* __restrict__ res_bn_gamma, const float* __restrict__ res_bn_beta) {
    __shared__ float ssum[128];
    __shared__ float ssq[128];
    int ch = blockIdx.x;
    int ob = ch >> 7, row = ch & 127;
    int tid = threadIdx.x;

    float s = 0.f, q = 0.f;
    // 400 partial blocks: n in 0..15, tvb in 0..24
    for (int e = tid; e < 400; e += 128) {
        int nn = e / 25, tvb = e - nn * 25;
        int blk = (nn * 2 + ob) * 25 + tvb;
        s += d_rpart[blk * 256 + row * 2];
        q += d_rpart[blk * 256 + row * 2 + 1];
    }
    ssum[tid] = s;
    ssq[tid] = q;
    __syncthreads();
    for (int st = 64; st > 0; st >>= 1) {
        if (tid < st) {
            ssum[tid] += ssum[tid + st];
            ssq[tid] += ssq[tid + st];
        }
        __syncthreads();
    }
    if (tid == 0) {
        const float inv = 1.f / 51200.f;
        float mean = ssum[0] * inv;
        float var = ssq[0] * inv - mean * mean;
        float sc = res_bn_gamma[ch] * rsqrtf(var + 1e-5f);
        d_ss[512 + ch] = sc;
        d_ss[768 + ch] = res_bn_beta[ch] - mean * sc;
    }
}

// ---------------------------------------------------------------------------
// Kernel 5: out = relu(BN(out_pre) + BN(res_pre)), float4.
// ---------------------------------------------------------------------------
__global__ __launch_bounds__(256) void final_kernel(float* __restrict__ out) {
    int idx4 = blockIdx.x * 256 + threadIdx.x;
    int flat = idx4 * 4;
    int ch = (flat / TV) & 255;
    float4 op = *(const float4*)(d_out_pre + flat);
    float4 rp = *(const float4*)(d_res_pre + flat);
    float so = d_ss[ch], ho = d_ss[256 + ch];
    float sr = d_ss[512 + ch], hr = d_ss[768 + ch];
    float4 r;
    r.x = fmaxf(fmaf(op.x, so, ho) + fmaf(rp.x, sr, hr), 0.f);
    r.y = fmaxf(fmaf(op.y, so, ho) + fmaf(rp.y, sr, hr), 0.f);
    r.z = fmaxf(fmaf(op.z, so, ho) + fmaf(rp.z, sr, hr), 0.f);
    r.w = fmaxf(fmaf(op.w, so, ho) + fmaf(rp.w, sr, hr), 0.f);
    *(float4*)(out + flat) = r;
}

// ---------------------------------------------------------------------------
extern "C" void kernel_launch(void* const* d_in, const int* in_sizes, int n_in,
                              void* d_out, int out_size) {
    const float* x            = (const float*)d_in[0];
    const int*   hop          = (const int*)d_in[1];
    const float* emb          = (const float*)d_in[2];
    const float* A            = (const float*)d_in[3];
    const float* w_block      = (const float*)d_in[4];
    const float* b_block      = (const float*)d_in[5];
    const float* bn_gamma     = (const float*)d_in[6];
    const float* bn_beta      = (const float*)d_in[7];
    const float* res_w        = (const float*)d_in[8];
    const float* res_b        = (const float*)d_in[9];
    const float* res_bn_gamma = (const float*)d_in[10];
    const float* res_bn_beta  = (const float*)d_in[11];
    float* out = (float*)d_out;

    cudaFuncSetAttribute(res_gemm_tc, cudaFuncAttributeMaxDynamicSharedMemorySize,
                         RES_SMEM_BYTES);

    prep_kernel<<<25, 32>>>(hop, emb, A, b_block);
    res_gemm_tc<<<dim3(25, 2, 16), 256, RES_SMEM_BYTES>>>(x, res_w, res_b);
    main_kernel<<<dim3(16, 8, 16), 200>>>(x, w_block);
    stats_kernel<<<256, 512>>>(bn_gamma, bn_beta);
    stats_res_kernel<<<256, 128>>>(res_bn_gamma, res_bn_beta);
    final_kernel<<<12800, 256>>>(out);
}